// round 15
// baseline (speedup 1.0000x reference)
#include <cuda_runtime.h>
#include <cuda_bf16.h>
#include <math.h>
#include <stdint.h>

#define BB 4
#define CC 1024
#define DD 1024
#define HH 16
#define DHH 64
#define ROWS (BB*CC)              // 4096
#define ELEMS (BB*CC*DD)          // 4194304
#define ATTN_ELEMS (BB*HH*CC*CC)  // 67108864

typedef __nv_bfloat16 bf;

// ---------------- scratch (__device__ globals; no allocation allowed) -------
__device__ float g_vp[ELEMS];
__device__ float g_proj[ELEMS];
__device__ float g_attn_scratch[ATTN_ELEMS];   // only if attn not in d_out
__device__ bf g_qh[ELEMS],  g_ql[ELEMS];
__device__ bf g_knh[ELEMS], g_knl[ELEMS];
__device__ bf g_vnh[ELEMS], g_vnl[ELEMS];
__device__ bf g_qph[ELEMS], g_qpl[ELEMS];
__device__ bf g_kph[ELEMS], g_kpl[ELEMS];
__device__ bf g_vth[ELEMS], g_vtl[ELEMS];
__device__ bf g_cxh[ELEMS], g_cxl[ELEMS];
__device__ bf g_bhi[4*DD*DD], g_blo[4*DD*DD];  // per-weight split buffers

// ---------------- PTX helpers ----------------------------------------------
__device__ __forceinline__ uint32_t smem_u32(const void* p) {
    uint32_t a;
    asm("{ .reg .u64 t; cvta.to.shared.u64 t, %1; cvt.u32.u64 %0, t; }"
        : "=r"(a) : "l"(p));
    return a;
}
__device__ __forceinline__ void ldmatrix_x4(uint32_t& r0, uint32_t& r1,
                                            uint32_t& r2, uint32_t& r3,
                                            uint32_t addr) {
    asm volatile("ldmatrix.sync.aligned.m8n8.x4.shared.b16 {%0,%1,%2,%3}, [%4];"
        : "=r"(r0), "=r"(r1), "=r"(r2), "=r"(r3) : "r"(addr));
}
__device__ __forceinline__ void mma_bf16(float* d, const uint32_t* a,
                                         uint32_t b0, uint32_t b1) {
    asm volatile(
        "mma.sync.aligned.m16n8k16.row.col.f32.bf16.bf16.f32 "
        "{%0,%1,%2,%3}, {%4,%5,%6,%7}, {%8,%9}, {%0,%1,%2,%3};"
        : "+f"(d[0]), "+f"(d[1]), "+f"(d[2]), "+f"(d[3])
        : "r"(a[0]), "r"(a[1]), "r"(a[2]), "r"(a[3]), "r"(b0), "r"(b1));
}
#define CP16(dst, src) \
    asm volatile("cp.async.cg.shared.global [%0], [%1], 16;" \
        :: "r"((uint32_t)(dst)), "l"(src))
#define CP_COMMIT() asm volatile("cp.async.commit_group;" ::: "memory")
#define CP_WAIT0()  asm volatile("cp.async.wait_group 0;" ::: "memory")
#define CP_WAIT1()  asm volatile("cp.async.wait_group 1;" ::: "memory")

__device__ __forceinline__ uint32_t pack_bf2(float x, float y) {
    union { __nv_bfloat162 b2; uint32_t u; } u;
    u.b2 = __halves2bfloat162(__float2bfloat16(x), __float2bfloat16(y));
    return u.u;
}

// ---------------------------------------------------------------------------
// Generic 128x128 HMMA core: C = A[M,K] @ B^T + bias
// ---------------------------------------------------------------------------
#define GP 40
#define STG 40960
#define AHOF 0
#define ALOF 10240
#define BHOF 20480
#define BLOF 30720

__device__ __forceinline__ void hgemm128_core(
    uint32_t sb,
    const bf* __restrict__ Ahi, const bf* __restrict__ Alo, int lda,
    const bf* __restrict__ Bhi, const bf* __restrict__ Blo, int ldb,
    const float* __restrict__ bias,
    float* __restrict__ Cf, int ldcf,
    bf* __restrict__ Chi, bf* __restrict__ Clo, int ldch,
    int Ktot, int m0, int n0)
{
    int tid = threadIdx.x, wid = tid >> 5, lane = tid & 31;
    int wm = (wid >> 2) * 64, wn = (wid & 3) * 32;
    float acc[4][4][4];
    #pragma unroll
    for (int i = 0; i < 4; i++)
        #pragma unroll
        for (int j = 0; j < 4; j++)
            #pragma unroll
            for (int q = 0; q < 4; q++) acc[i][j][q] = 0.f;

    int a_row = lane & 15, a_k8 = lane >> 4;
    int b_n = (lane >> 4) * 8 + (lane & 7), b_k8 = (lane >> 3) & 1;
    int r0 = tid >> 2, c0 = tid & 3;

    auto do_load = [&](int kt, int s) {
        uint32_t base = sb + s * STG;
        #pragma unroll
        for (int i = 0; i < 2; i++) {
            int row = r0 + i * 64;
            uint32_t so = (uint32_t)(row * GP + c0 * 8) * 2;
            size_t ga = (size_t)(m0 + row) * lda + kt * 32 + c0 * 8;
            size_t gb = (size_t)(n0 + row) * ldb + kt * 32 + c0 * 8;
            CP16(base + AHOF + so, Ahi + ga);
            CP16(base + ALOF + so, Alo + ga);
            CP16(base + BHOF + so, Bhi + gb);
            CP16(base + BLOF + so, Blo + gb);
        }
    };
    auto do_compute = [&](int s) {
        uint32_t base = sb + s * STG;
        #pragma unroll
        for (int kk = 0; kk < 32; kk += 16) {
            uint32_t bh[2][4], bl[2][4];
            #pragma unroll
            for (int bt = 0; bt < 2; bt++) {
                uint32_t off = (uint32_t)((wn + bt * 16 + b_n) * GP
                                          + kk + b_k8 * 8) * 2;
                ldmatrix_x4(bh[bt][0], bh[bt][1], bh[bt][2], bh[bt][3],
                            base + BHOF + off);
                ldmatrix_x4(bl[bt][0], bl[bt][1], bl[bt][2], bl[bt][3],
                            base + BLOF + off);
            }
            #pragma unroll
            for (int mh = 0; mh < 2; mh++) {
                uint32_t ah[2][4], al[2][4];
                #pragma unroll
                for (int m2 = 0; m2 < 2; m2++) {
                    int mt = mh * 2 + m2;
                    uint32_t off = (uint32_t)((wm + mt * 16 + a_row) * GP
                                              + kk + a_k8 * 8) * 2;
                    ldmatrix_x4(ah[m2][0], ah[m2][1], ah[m2][2], ah[m2][3],
                                base + AHOF + off);
                    ldmatrix_x4(al[m2][0], al[m2][1], al[m2][2], al[m2][3],
                                base + ALOF + off);
                }
                #pragma unroll
                for (int m2 = 0; m2 < 2; m2++) {
                    int mt = mh * 2 + m2;
                    #pragma unroll
                    for (int nt = 0; nt < 4; nt++) {
                        int bt = nt >> 1, hf = (nt & 1) * 2;
                        mma_bf16(acc[mt][nt], ah[m2], bh[bt][hf], bh[bt][hf + 1]);
                        mma_bf16(acc[mt][nt], ah[m2], bl[bt][hf], bl[bt][hf + 1]);
                        mma_bf16(acc[mt][nt], al[m2], bh[bt][hf], bh[bt][hf + 1]);
                    }
                }
            }
        }
    };

    int nch = Ktot / 32;
    do_load(0, 0); CP_COMMIT();
    for (int kt = 0; kt < nch; kt++) {
        int cur = kt & 1;
        if (kt + 1 < nch) { do_load(kt + 1, cur ^ 1); CP_COMMIT(); CP_WAIT1(); }
        else              { CP_WAIT0(); }
        __syncthreads();
        do_compute(cur);
        __syncthreads();
    }

    int gr = lane >> 2, gc2 = (lane & 3) * 2;
    #pragma unroll
    for (int mt = 0; mt < 4; mt++) {
        int r = m0 + wm + mt * 16 + gr;
        #pragma unroll
        for (int nt = 0; nt < 4; nt++) {
            int c = n0 + wn + nt * 8 + gc2;
            float bx = 0.f, by = 0.f;
            if (bias) { float2 b2 = *(const float2*)(bias + c); bx = b2.x; by = b2.y; }
            float v00 = acc[mt][nt][0] + bx, v01 = acc[mt][nt][1] + by;
            float v10 = acc[mt][nt][2] + bx, v11 = acc[mt][nt][3] + by;
            if (Cf) {
                *(float2*)(Cf + (size_t)r * ldcf + c)       = make_float2(v00, v01);
                *(float2*)(Cf + (size_t)(r + 8) * ldcf + c) = make_float2(v10, v11);
            }
            if (Chi) {
                bf h00 = __float2bfloat16(v00), h01 = __float2bfloat16(v01);
                bf h10 = __float2bfloat16(v10), h11 = __float2bfloat16(v11);
                *(__nv_bfloat162*)(Chi + (size_t)r * ldch + c) =
                    __halves2bfloat162(h00, h01);
                *(__nv_bfloat162*)(Chi + (size_t)(r + 8) * ldch + c) =
                    __halves2bfloat162(h10, h11);
                *(__nv_bfloat162*)(Clo + (size_t)r * ldch + c) = __halves2bfloat162(
                    __float2bfloat16(v00 - __bfloat162float(h00)),
                    __float2bfloat16(v01 - __bfloat162float(h01)));
                *(__nv_bfloat162*)(Clo + (size_t)(r + 8) * ldch + c) = __halves2bfloat162(
                    __float2bfloat16(v10 - __bfloat162float(h10)),
                    __float2bfloat16(v11 - __bfloat162float(h11)));
            }
        }
    }
}

__global__ __launch_bounds__(256, 2) void hgemm_proj(
    const bf* __restrict__ Ahi, const bf* __restrict__ Alo,
    const bf* __restrict__ Bhi, const bf* __restrict__ Blo,
    const float* __restrict__ bias,
    float* __restrict__ Cf, bf* __restrict__ Chi, bf* __restrict__ Clo)
{
    extern __shared__ char smem[];
    hgemm128_core(smem_u32(smem), Ahi, Alo, DD, Bhi, Blo, DD, bias,
                  Cf, DD, Chi, Clo, DD, DD,
                  blockIdx.y * 128, blockIdx.x * 128);
}

// scores: per (b,h): raw = qh @ kh^T (fp32 out, no activation)
__global__ __launch_bounds__(256, 2) void hgemm_scores(
    const bf* __restrict__ qph, const bf* __restrict__ qpl,
    const bf* __restrict__ kph, const bf* __restrict__ kpl,
    float* __restrict__ attn)
{
    extern __shared__ char smem[];
    int bh = blockIdx.z, b = bh >> 4, h = bh & 15;
    size_t off = (size_t)b * CC * DD + h * DHH;
    hgemm128_core(smem_u32(smem), qph + off, qpl + off, DD,
                  kph + off, kpl + off, DD, nullptr,
                  attn + (size_t)bh * CC * CC, CC,
                  nullptr, nullptr, 0, DHH,
                  blockIdx.y * 128, blockIdx.x * 128);
}

// ---------------------------------------------------------------------------
// ctx from fp32 P: ctx = P @ vt^T; hi/lo bf16 A-fragments built in registers.
// ---------------------------------------------------------------------------
#define XPA 0
#define XBH 18432
#define XBL 23552
#define XSTG 28672

__global__ __launch_bounds__(256, 2) void hgemm_ctx_f32p(
    const float* __restrict__ P,
    const bf* __restrict__ Bh, const bf* __restrict__ Bl,
    bf* __restrict__ Chi, bf* __restrict__ Clo)
{
    extern __shared__ char smem[];
    uint32_t sb = smem_u32(smem);
    int bh = blockIdx.z, b = bh >> 4, h = bh & 15;
    const float* A  = P  + (size_t)bh * CC * CC;
    const bf* Bhi = Bh + (size_t)(b * CC + h * DHH) * CC;
    const bf* Blo = Bl + (size_t)(b * CC + h * DHH) * CC;
    int m0 = blockIdx.y * 128;

    int tid = threadIdx.x, wid = tid >> 5, lane = tid & 31;
    int wm = (wid >> 1) * 32, wn = (wid & 1) * 32;
    float acc[2][4][4];
    #pragma unroll
    for (int i = 0; i < 2; i++)
        #pragma unroll
        for (int j = 0; j < 4; j++)
            #pragma unroll
            for (int q = 0; q < 4; q++) acc[i][j][q] = 0.f;

    int b_n = (lane >> 4) * 8 + (lane & 7), b_k8 = (lane >> 3) & 1;

    auto do_load = [&](int kt, int s) {
        uint32_t base = sb + s * XSTG;
        #pragma unroll
        for (int i = 0; i < 4; i++) {
            int idx = tid + i * 256;
            int row = idx >> 3, u = idx & 7;
            CP16(base + XPA + row * 144 + u * 16,
                 A + (size_t)(m0 + row) * CC + kt * 32 + u * 4);
        }
        {
            int row = tid >> 2, c = tid & 3;
            uint32_t so = (uint32_t)(row * GP + c * 8) * 2;
            size_t gb = (size_t)row * CC + kt * 32 + c * 8;
            CP16(base + XBH + so, Bhi + gb);
            CP16(base + XBL + so, Blo + gb);
        }
    };
    auto do_compute = [&](int s) {
        uint32_t base = sb + s * XSTG;
        const float* As = (const float*)(smem + s * XSTG + XPA);
        #pragma unroll
        for (int kk = 0; kk < 32; kk += 16) {
            uint32_t bh2[2][4], bl2[2][4];
            #pragma unroll
            for (int bt = 0; bt < 2; bt++) {
                uint32_t off = (uint32_t)((wn + bt * 16 + b_n) * GP
                                          + kk + b_k8 * 8) * 2;
                ldmatrix_x4(bh2[bt][0], bh2[bt][1], bh2[bt][2], bh2[bt][3],
                            base + XBH + off);
                ldmatrix_x4(bl2[bt][0], bl2[bt][1], bl2[bt][2], bl2[bt][3],
                            base + XBL + off);
            }
            #pragma unroll
            for (int mt = 0; mt < 2; mt++) {
                int r = wm + mt * 16 + (lane >> 2);
                int c0 = kk + (lane & 3) * 2;
                float2 p0 = *(const float2*)(As + r * 36 + c0);
                float2 p1 = *(const float2*)(As + (r + 8) * 36 + c0);
                float2 p2 = *(const float2*)(As + r * 36 + c0 + 8);
                float2 p3 = *(const float2*)(As + (r + 8) * 36 + c0 + 8);
                uint32_t a_hi[4], a_lo[4];
                a_hi[0] = pack_bf2(p0.x, p0.y);
                a_hi[1] = pack_bf2(p1.x, p1.y);
                a_hi[2] = pack_bf2(p2.x, p2.y);
                a_hi[3] = pack_bf2(p3.x, p3.y);
                bf h0x = __float2bfloat16(p0.x), h0y = __float2bfloat16(p0.y);
                bf h1x = __float2bfloat16(p1.x), h1y = __float2bfloat16(p1.y);
                bf h2x = __float2bfloat16(p2.x), h2y = __float2bfloat16(p2.y);
                bf h3x = __float2bfloat16(p3.x), h3y = __float2bfloat16(p3.y);
                a_lo[0] = pack_bf2(p0.x - __bfloat162float(h0x),
                                   p0.y - __bfloat162float(h0y));
                a_lo[1] = pack_bf2(p1.x - __bfloat162float(h1x),
                                   p1.y - __bfloat162float(h1y));
                a_lo[2] = pack_bf2(p2.x - __bfloat162float(h2x),
                                   p2.y - __bfloat162float(h2y));
                a_lo[3] = pack_bf2(p3.x - __bfloat162float(h3x),
                                   p3.y - __bfloat162float(h3y));
                #pragma unroll
                for (int nt = 0; nt < 4; nt++) {
                    int bt = nt >> 1, hf = (nt & 1) * 2;
                    mma_bf16(acc[mt][nt], a_hi, bh2[bt][hf], bh2[bt][hf + 1]);
                    mma_bf16(acc[mt][nt], a_lo, bh2[bt][hf], bh2[bt][hf + 1]);
                    mma_bf16(acc[mt][nt], a_hi, bl2[bt][hf], bl2[bt][hf + 1]);
                }
            }
        }
    };

    int nch = CC / 32;
    do_load(0, 0); CP_COMMIT();
    for (int kt = 0; kt < nch; kt++) {
        int cur = kt & 1;
        if (kt + 1 < nch) { do_load(kt + 1, cur ^ 1); CP_COMMIT(); CP_WAIT1(); }
        else              { CP_WAIT0(); }
        __syncthreads();
        do_compute(cur);
        __syncthreads();
    }

    int gr = lane >> 2, gc2 = (lane & 3) * 2;
    #pragma unroll
    for (int mt = 0; mt < 2; mt++) {
        int r = m0 + wm + mt * 16 + gr;
        size_t grow0 = (size_t)(b * CC + r) * DD;
        size_t grow1 = (size_t)(b * CC + r + 8) * DD;
        #pragma unroll
        for (int nt = 0; nt < 4; nt++) {
            int c = h * DHH + wn + nt * 8 + gc2;
            float v00 = acc[mt][nt][0], v01 = acc[mt][nt][1];
            float v10 = acc[mt][nt][2], v11 = acc[mt][nt][3];
            bf h00 = __float2bfloat16(v00), h01 = __float2bfloat16(v01);
            bf h10 = __float2bfloat16(v10), h11 = __float2bfloat16(v11);
            *(__nv_bfloat162*)(Chi + grow0 + c) = __halves2bfloat162(h00, h01);
            *(__nv_bfloat162*)(Chi + grow1 + c) = __halves2bfloat162(h10, h11);
            *(__nv_bfloat162*)(Clo + grow0 + c) = __halves2bfloat162(
                __float2bfloat16(v00 - __bfloat162float(h00)),
                __float2bfloat16(v01 - __bfloat162float(h01)));
            *(__nv_bfloat162*)(Clo + grow1 + c) = __halves2bfloat162(
                __float2bfloat16(v10 - __bfloat162float(h10)),
                __float2bfloat16(v11 - __bfloat162float(h11)));
        }
    }
}

// ---------------------------------------------------------------------------
// FLASH-FUSED attention (only used when attn is NOT part of d_out)
// ---------------------------------------------------------------------------
#define QSTR 72
#define VSTR 72
#define FQH 0
#define FQL 18432
#define FKH(s) (36864 + (s) * 18432)
#define FKL(s) (FKH(s) + 9216)
#define FVH(s) (73728 + (s) * 18432)
#define FVL(s) (FVH(s) + 9216)
#define FSMEM 110592

__global__ __launch_bounds__(256, 2) void flash_attn_kernel(
    const bf* __restrict__ qph, const bf* __restrict__ qpl,
    const bf* __restrict__ kph, const bf* __restrict__ kpl,
    const bf* __restrict__ vth, const bf* __restrict__ vtl,
    bf* __restrict__ cxh, bf* __restrict__ cxl)
{
    extern __shared__ char smem[];
    uint32_t sb = smem_u32(smem);
    int bh = blockIdx.z, b = bh >> 4, h = bh & 15;
    int m0 = blockIdx.y * 128;
    int tid = threadIdx.x, wid = tid >> 5, lane = tid & 31;
    int wm = wid * 16;

    const bf* Qh = qph + (size_t)b * CC * DD + h * DHH;
    const bf* Ql = qpl + (size_t)b * CC * DD + h * DHH;
    const bf* Kh = kph + (size_t)b * CC * DD + h * DHH;
    const bf* Kl = kpl + (size_t)b * CC * DD + h * DHH;
    const bf* Vh = vth + (size_t)(b * CC + h * DHH) * CC;
    const bf* Vl = vtl + (size_t)(b * CC + h * DHH) * CC;

    auto loadQ = [&]() {
        #pragma unroll
        for (int i = 0; i < 4; i++) {
            int idx = tid + i * 256;
            int row = idx >> 3, c8 = idx & 7;
            uint32_t so = (uint32_t)(row * QSTR + c8 * 8) * 2;
            size_t g = (size_t)(m0 + row) * DD + c8 * 8;
            CP16(sb + FQH + so, Qh + g);
            CP16(sb + FQL + so, Ql + g);
        }
    };
    auto loadK = [&](int kb, int s) {
        #pragma unroll
        for (int i = 0; i < 2; i++) {
            int idx = tid + i * 256;
            int row = idx >> 3, c8 = idx & 7;
            uint32_t so = (uint32_t)(row * QSTR + c8 * 8) * 2;
            size_t g = (size_t)(kb * 64 + row) * DD + c8 * 8;
            CP16(sb + FKH(s) + so, Kh + g);
            CP16(sb + FKL(s) + so, Kl + g);
        }
    };
    auto loadV = [&](int kb, int s) {
        #pragma unroll
        for (int i = 0; i < 2; i++) {
            int idx = tid + i * 256;
            int row = idx >> 3, c8 = idx & 7;
            uint32_t so = (uint32_t)(row * VSTR + c8 * 8) * 2;
            size_t g = (size_t)row * CC + kb * 64 + c8 * 8;
            CP16(sb + FVH(s) + so, Vh + g);
            CP16(sb + FVL(s) + so, Vl + g);
        }
    };

    float O[8][4];
    #pragma unroll
    for (int g = 0; g < 8; g++)
        #pragma unroll
        for (int q = 0; q < 4; q++) O[g][q] = 0.f;
    float s_run0 = 0.f, s_run1 = 0.f;

    int a_row = lane & 15, a_k8 = lane >> 4;
    int b_n = (lane >> 4) * 8 + (lane & 7), b_k8 = (lane >> 3) & 1;

    loadQ(); loadK(0, 0); loadV(0, 0); CP_COMMIT();

    for (int kb = 0; kb < 16; kb++) {
        int s = kb & 1;
        if (kb < 15) { loadK(kb + 1, s ^ 1); loadV(kb + 1, s ^ 1); CP_COMMIT(); CP_WAIT1(); }
        else         { CP_WAIT0(); }
        __syncthreads();

        #pragma unroll
        for (int sub = 0; sub < 2; sub++) {
            float acc[4][4];
            #pragma unroll
            for (int nt = 0; nt < 4; nt++)
                #pragma unroll
                for (int q = 0; q < 4; q++) acc[nt][q] = 0.f;

            #pragma unroll
            for (int ks = 0; ks < 4; ks++) {
                uint32_t qh4[4], ql4[4];
                uint32_t offA = (uint32_t)((wm + a_row) * QSTR + ks * 16 + a_k8 * 8) * 2;
                ldmatrix_x4(qh4[0], qh4[1], qh4[2], qh4[3], sb + FQH + offA);
                ldmatrix_x4(ql4[0], ql4[1], ql4[2], ql4[3], sb + FQL + offA);
                #pragma unroll
                for (int g2 = 0; g2 < 2; g2++) {
                    int g = sub * 2 + g2;
                    uint32_t bh4[4], bl4[4];
                    uint32_t offB = (uint32_t)((g * 16 + b_n) * QSTR + ks * 16 + b_k8 * 8) * 2;
                    ldmatrix_x4(bh4[0], bh4[1], bh4[2], bh4[3], sb + FKH(s) + offB);
                    ldmatrix_x4(bl4[0], bl4[1], bl4[2], bl4[3], sb + FKL(s) + offB);
                    mma_bf16(acc[g2 * 2],     qh4, bh4[0], bh4[1]);
                    mma_bf16(acc[g2 * 2 + 1], qh4, bh4[2], bh4[3]);
                    mma_bf16(acc[g2 * 2],     qh4, bl4[0], bl4[1]);
                    mma_bf16(acc[g2 * 2 + 1], qh4, bl4[2], bl4[3]);
                    mma_bf16(acc[g2 * 2],     ql4, bh4[0], bh4[1]);
                    mma_bf16(acc[g2 * 2 + 1], ql4, bh4[2], bh4[3]);
                }
            }

            #pragma unroll
            for (int nt = 0; nt < 4; nt++)
                #pragma unroll
                for (int q = 0; q < 4; q++) {
                    float x = acc[nt][q];
                    float x2 = x * x;
                    float u = __fmaf_rn(0.044715f, x2, 1.0f);
                    float e = __expf(-1.5957691216f * x * u);
                    float sig = __frcp_rn(1.0f + e);
                    acc[nt][q] = __expf(0.125f * x * sig);
                }
            #pragma unroll
            for (int nt = 0; nt < 4; nt++) {
                s_run0 += acc[nt][0] + acc[nt][1];
                s_run1 += acc[nt][2] + acc[nt][3];
            }

            #pragma unroll
            for (int ks2 = 0; ks2 < 2; ks2++) {
                int t0 = ks2 * 2, t1 = t0 + 1;
                uint32_t a_hi[4], a_lo[4];
                {
                    float x0 = acc[t0][0], x1 = acc[t0][1];
                    float x2 = acc[t0][2], x3 = acc[t0][3];
                    float y0 = acc[t1][0], y1 = acc[t1][1];
                    float y2 = acc[t1][2], y3 = acc[t1][3];
                    a_hi[0] = pack_bf2(x0, x1);
                    a_hi[1] = pack_bf2(x2, x3);
                    a_hi[2] = pack_bf2(y0, y1);
                    a_hi[3] = pack_bf2(y2, y3);
                    bf hx0 = __float2bfloat16(x0), hx1 = __float2bfloat16(x1);
                    bf hx2 = __float2bfloat16(x2), hx3 = __float2bfloat16(x3);
                    bf hy0 = __float2bfloat16(y0), hy1 = __float2bfloat16(y1);
                    bf hy2 = __float2bfloat16(y2), hy3 = __float2bfloat16(y3);
                    a_lo[0] = pack_bf2(x0 - __bfloat162float(hx0),
                                       x1 - __bfloat162float(hx1));
                    a_lo[1] = pack_bf2(x2 - __bfloat162float(hx2),
                                       x3 - __bfloat162float(hx3));
                    a_lo[2] = pack_bf2(y0 - __bfloat162float(hy0),
                                       y1 - __bfloat162float(hy1));
                    a_lo[3] = pack_bf2(y2 - __bfloat162float(hy2),
                                       y3 - __bfloat162float(hy3));
                }
                int kstep = sub * 2 + ks2;
                #pragma unroll
                for (int g = 0; g < 4; g++) {
                    uint32_t vh4[4], vl4[4];
                    uint32_t offV = (uint32_t)((g * 16 + b_n) * VSTR
                                               + kstep * 16 + b_k8 * 8) * 2;
                    ldmatrix_x4(vh4[0], vh4[1], vh4[2], vh4[3], sb + FVH(s) + offV);
                    ldmatrix_x4(vl4[0], vl4[1], vl4[2], vl4[3], sb + FVL(s) + offV);
                    mma_bf16(O[g * 2],     a_hi, vh4[0], vh4[1]);
                    mma_bf16(O[g * 2 + 1], a_hi, vh4[2], vh4[3]);
                    mma_bf16(O[g * 2],     a_lo, vh4[0], vh4[1]);
                    mma_bf16(O[g * 2 + 1], a_lo, vh4[2], vh4[3]);
                    mma_bf16(O[g * 2],     a_hi, vl4[0], vl4[1]);
                    mma_bf16(O[g * 2 + 1], a_hi, vl4[2], vl4[3]);
                }
            }
        }
        __syncthreads();
    }

    #pragma unroll
    for (int o = 1; o <= 2; o <<= 1) {
        s_run0 += __shfl_xor_sync(0xFFFFFFFFu, s_run0, o);
        s_run1 += __shfl_xor_sync(0xFFFFFFFFu, s_run1, o);
    }
    float i0 = 1.f / s_run0, i1 = 1.f / s_run1;
    int r = m0 + wm + (lane >> 2);
    size_t row0 = (size_t)(b * CC + r) * DD;
    size_t row1 = (size_t)(b * CC + r + 8) * DD;
    #pragma unroll
    for (int g = 0; g < 8; g++) {
        int c = h * DHH + g * 8 + (lane & 3) * 2;
        float v00 = O[g][0] * i0, v01 = O[g][1] * i0;
        float v10 = O[g][2] * i1, v11 = O[g][3] * i1;
        bf h00 = __float2bfloat16(v00), h01 = __float2bfloat16(v01);
        bf h10 = __float2bfloat16(v10), h11 = __float2bfloat16(v11);
        *(__nv_bfloat162*)(cxh + row0 + c) = __halves2bfloat162(h00, h01);
        *(__nv_bfloat162*)(cxh + row1 + c) = __halves2bfloat162(h10, h11);
        *(__nv_bfloat162*)(cxl + row0 + c) = __halves2bfloat162(
            __float2bfloat16(v00 - __bfloat162float(h00)),
            __float2bfloat16(v01 - __bfloat162float(h01)));
        *(__nv_bfloat162*)(cxl + row1 + c) = __halves2bfloat162(
            __float2bfloat16(v10 - __bfloat162float(h10)),
            __float2bfloat16(v11 - __bfloat162float(h11)));
    }
}

// ---------------------------------------------------------------------------
// elementwise / reduction kernels
// ---------------------------------------------------------------------------
__global__ __launch_bounds__(256) void split_kernel(
    const float* __restrict__ x, bf* __restrict__ hi, bf* __restrict__ lo)
{
    int i = blockIdx.x * 256 + threadIdx.x;
    float4 v = ((const float4*)x)[i];
    bf h0 = __float2bfloat16(v.x), h1 = __float2bfloat16(v.y);
    bf h2 = __float2bfloat16(v.z), h3 = __float2bfloat16(v.w);
    union { __nv_bfloat162 b2[2]; uint2 u; } ph, pl;
    ph.b2[0] = __halves2bfloat162(h0, h1); ph.b2[1] = __halves2bfloat162(h2, h3);
    pl.b2[0] = __halves2bfloat162(__float2bfloat16(v.x - __bfloat162float(h0)),
                                  __float2bfloat16(v.y - __bfloat162float(h1)));
    pl.b2[1] = __halves2bfloat162(__float2bfloat16(v.z - __bfloat162float(h2)),
                                  __float2bfloat16(v.w - __bfloat162float(h3)));
    ((uint2*)hi)[i] = ph.u;
    ((uint2*)lo)[i] = pl.u;
}

__global__ void split_wt_kernel(const float* __restrict__ W,
                                bf* __restrict__ hiT, bf* __restrict__ loT)
{
    __shared__ float t[32][33];
    int k0 = blockIdx.y * 32, n0 = blockIdx.x * 32;
    int tx = threadIdx.x, ty = threadIdx.y;
    #pragma unroll
    for (int j = 0; j < 4; j++)
        t[ty + j * 8][tx] = W[(size_t)(k0 + ty + j * 8) * DD + n0 + tx];
    __syncthreads();
    #pragma unroll
    for (int j = 0; j < 4; j++) {
        float x = t[tx][ty + j * 8];
        bf h = __float2bfloat16(x);
        size_t o = (size_t)(n0 + ty + j * 8) * DD + k0 + tx;
        hiT[o] = h;
        loT[o] = __float2bfloat16(x - __bfloat162float(h));
    }
}

__global__ void transpose_split_kernel(const float* __restrict__ vp,
                                       bf* __restrict__ vth, bf* __restrict__ vtl)
{
    __shared__ float t[32][33];
    int b = blockIdx.z;
    int c0 = blockIdx.x * 32, n0 = blockIdx.y * 32;
    int tx = threadIdx.x, ty = threadIdx.y;
    #pragma unroll
    for (int j = 0; j < 4; j++)
        t[ty + j * 8][tx] = vp[(size_t)(b * CC + c0 + ty + j * 8) * DD + n0 + tx];
    __syncthreads();
    #pragma unroll
    for (int j = 0; j < 4; j++) {
        float x = t[tx][ty + j * 8];
        bf h = __float2bfloat16(x);
        size_t o = (size_t)(b * CC + n0 + ty + j * 8) * CC + c0 + tx;
        vth[o] = h;
        vtl[o] = __float2bfloat16(x - __bfloat162float(h));
    }
}

__global__ __launch_bounds__(256) void ln_bf16_kernel(
    const float* __restrict__ x, const float* __restrict__ gam,
    const float* __restrict__ bet, bf* __restrict__ oh, bf* __restrict__ ol)
{
    int row = blockIdx.x;
    int tid = threadIdx.x;
    const float4 v = ((const float4*)(x + (size_t)row * DD))[tid];
    float s  = v.x + v.y + v.z + v.w;
    float ss = v.x*v.x + v.y*v.y + v.z*v.z + v.w*v.w;
    #pragma unroll
    for (int o = 16; o > 0; o >>= 1) {
        s  += __shfl_xor_sync(0xFFFFFFFFu, s, o);
        ss += __shfl_xor_sync(0xFFFFFFFFu, ss, o);
    }
    __shared__ float sh_s[8], sh_ss[8];
    __shared__ float sh_m, sh_r;
    int w = tid >> 5, l = tid & 31;
    if (l == 0) { sh_s[w] = s; sh_ss[w] = ss; }
    __syncthreads();
    if (tid == 0) {
        float S = 0.f, SS = 0.f;
        #pragma unroll
        for (int i = 0; i < 8; i++) { S += sh_s[i]; SS += sh_ss[i]; }
        float m = S * (1.0f / DD);
        sh_m = m;
        sh_r = rsqrtf(SS * (1.0f / DD) - m * m + 1e-5f);
    }
    __syncthreads();
    float m = sh_m, r = sh_r;
    const float4 g4 = ((const float4*)gam)[tid];
    const float4 b4 = ((const float4*)bet)[tid];
    float y0 = (v.x - m) * r * g4.x + b4.x;
    float y1 = (v.y - m) * r * g4.y + b4.y;
    float y2 = (v.z - m) * r * g4.z + b4.z;
    float y3 = (v.w - m) * r * g4.w + b4.w;
    bf h0 = __float2bfloat16(y0), h1 = __float2bfloat16(y1);
    bf h2 = __float2bfloat16(y2), h3 = __float2bfloat16(y3);
    union { __nv_bfloat162 b2[2]; uint2 u; } ph, pl;
    ph.b2[0] = __halves2bfloat162(h0, h1); ph.b2[1] = __halves2bfloat162(h2, h3);
    pl.b2[0] = __halves2bfloat162(__float2bfloat16(y0 - __bfloat162float(h0)),
                                  __float2bfloat16(y1 - __bfloat162float(h1)));
    pl.b2[1] = __halves2bfloat162(__float2bfloat16(y2 - __bfloat162float(h2)),
                                  __float2bfloat16(y3 - __bfloat162float(h3)));
    ((uint2*)(oh + (size_t)row * DD))[tid] = ph.u;
    ((uint2*)(ol + (size_t)row * DD))[tid] = pl.u;
}

// GELU*scale + softmax (no max pass: logits bounded <= ~4.5, exp safe)
__global__ __launch_bounds__(256) void softmax_kernel(
    const float* __restrict__ in, float* __restrict__ outf)
{
    size_t row = blockIdx.x;
    const float* r = in + row * (size_t)CC;
    int tid = threadIdx.x;
    float4 v = ((const float4*)r)[tid];
    const float scale = 0.125f;
    const float inv_sqrt2 = 0.70710678118654752f;
    float t0 = 0.5f * v.x * (1.0f + erff(v.x * inv_sqrt2)) * scale;
    float t1 = 0.5f * v.y * (1.0f + erff(v.y * inv_sqrt2)) * scale;
    float t2 = 0.5f * v.z * (1.0f + erff(v.z * inv_sqrt2)) * scale;
    float t3 = 0.5f * v.w * (1.0f + erff(v.w * inv_sqrt2)) * scale;

    float e0 = __expf(t0), e1 = __expf(t1);
    float e2 = __expf(t2), e3 = __expf(t3);
    float s = e0 + e1 + e2 + e3;
    #pragma unroll
    for (int o = 16; o > 0; o >>= 1)
        s += __shfl_xor_sync(0xFFFFFFFFu, s, o);
    __shared__ float shm[8];
    __shared__ float shv;
    int w = tid >> 5, l = tid & 31;
    if (l == 0) shm[w] = s;
    __syncthreads();
    if (tid == 0) {
        float S = 0.f;
        #pragma unroll
        for (int i = 0; i < 8; i++) S += shm[i];
        shv = 1.0f / S;
    }
    __syncthreads();
    float inv = shv;
    float4 o4;
    o4.x = e0 * inv; o4.y = e1 * inv; o4.z = e2 * inv; o4.w = e3 * inv;
    ((float4*)(outf + row * (size_t)CC))[tid] = o4;
}

__global__ __launch_bounds__(256) void l2norm_kernel(
    const float* __restrict__ x, float* __restrict__ y)
{
    int row = blockIdx.x;
    int tid = threadIdx.x;
    const float4 v = ((const float4*)(x + (size_t)row * DD))[tid];
    float ss = v.x*v.x + v.y*v.y + v.z*v.z + v.w*v.w;
    #pragma unroll
    for (int o = 16; o > 0; o >>= 1)
        ss += __shfl_xor_sync(0xFFFFFFFFu, ss, o);
    __shared__ float sh[8];
    __shared__ float shinv;
    int w = tid >> 5, l = tid & 31;
    if (l == 0) sh[w] = ss;
    __syncthreads();
    if (tid == 0) {
        float S = 0.f;
        #pragma unroll
        for (int i = 0; i < 8; i++) S += sh[i];
        shinv = 1.0f / fmaxf(sqrtf(S), 1e-12f);
    }
    __syncthreads();
    float inv = shinv;
    float4 o;
    o.x = v.x * inv; o.y = v.y * inv; o.z = v.z * inv; o.w = v.w * inv;
    ((float4*)(y + (size_t)row * DD))[tid] = o;
}

// ---------------------------------------------------------------------------
extern "C" void kernel_launch(void* const* d_in, const int* in_sizes, int n_in,
                              void* d_out, int out_size)
{
    const float* q      = (const float*)d_in[0];
    const float* k      = (const float*)d_in[1];
    const float* v      = (const float*)d_in[2];
    const float* ln_k_g = (const float*)d_in[3];
    const float* ln_k_b = (const float*)d_in[4];
    const float* ln_v_g = (const float*)d_in[5];
    const float* ln_v_b = (const float*)d_in[6];
    const float* Wq     = (const float*)d_in[7];
    const float* bq     = (const float*)d_in[8];
    const float* Wk     = (const float*)d_in[9];
    const float* bk     = (const float*)d_in[10];
    const float* Wv     = (const float*)d_in[11];
    const float* bv     = (const float*)d_in[12];
    const float* Wo     = (const float*)d_in[13];
    const float* bo     = (const float*)d_in[14];

    float* out = (float*)d_out;

    float *vp, *proj, *attn_scr;
    bf *qh, *ql, *knh, *knl, *vnh, *vnl, *qph, *qpl, *kph, *kpl;
    bf *vth, *vtl, *cxh, *cxl, *bhi, *blo;
    cudaGetSymbolAddress((void**)&vp,   g_vp);
    cudaGetSymbolAddress((void**)&proj, g_proj);
    cudaGetSymbolAddress((void**)&attn_scr, g_attn_scratch);
    cudaGetSymbolAddress((void**)&qh,  g_qh);  cudaGetSymbolAddress((void**)&ql,  g_ql);
    cudaGetSymbolAddress((void**)&knh, g_knh); cudaGetSymbolAddress((void**)&knl, g_knl);
    cudaGetSymbolAddress((void**)&vnh, g_vnh); cudaGetSymbolAddress((void**)&vnl, g_vnl);
    cudaGetSymbolAddress((void**)&qph, g_qph); cudaGetSymbolAddress((void**)&qpl, g_qpl);
    cudaGetSymbolAddress((void**)&kph, g_kph); cudaGetSymbolAddress((void**)&kpl, g_kpl);
    cudaGetSymbolAddress((void**)&vth, g_vth); cudaGetSymbolAddress((void**)&vtl, g_vtl);
    cudaGetSymbolAddress((void**)&cxh, g_cxh); cudaGetSymbolAddress((void**)&cxl, g_cxl);
    cudaGetSymbolAddress((void**)&bhi, g_bhi); cudaGetSymbolAddress((void**)&blo, g_blo);

    bf *bh_q = bhi,                   *bl_q = blo;
    bf *bh_k = bhi + (size_t)DD*DD,   *bl_k = blo + (size_t)DD*DD;
    bf *bh_v = bhi + (size_t)2*DD*DD, *bl_v = blo + (size_t)2*DD*DD;
    bf *bh_o = bhi + (size_t)3*DD*DD, *bl_o = blo + (size_t)3*DD*DD;

    int attn_in_out = (out_size >= (int)(ELEMS + ATTN_ELEMS));

    // Streams/events: created once on the first (uncaptured, correctness) call.
    static cudaStream_t s1 = nullptr, s2 = nullptr;
    static cudaEvent_t ev0 = nullptr, evK = nullptr, evV = nullptr;
    if (!s1) {
        cudaStreamCreateWithFlags(&s1, cudaStreamNonBlocking);
        cudaStreamCreateWithFlags(&s2, cudaStreamNonBlocking);
        cudaEventCreateWithFlags(&ev0, cudaEventDisableTiming);
        cudaEventCreateWithFlags(&evK, cudaEventDisableTiming);
        cudaEventCreateWithFlags(&evV, cudaEventDisableTiming);
    }

    cudaFuncSetAttribute(hgemm_proj,
        cudaFuncAttributeMaxDynamicSharedMemorySize, 2 * STG);
    cudaFuncSetAttribute(hgemm_scores,
        cudaFuncAttributeMaxDynamicSharedMemorySize, 2 * STG);
    cudaFuncSetAttribute(hgemm_ctx_f32p,
        cudaFuncAttributeMaxDynamicSharedMemorySize, 2 * XSTG);
    cudaFuncSetAttribute(flash_attn_kernel,
        cudaFuncAttributeMaxDynamicSharedMemorySize, FSMEM);

    dim3 gmm(DD / 128, ROWS / 128);      // (8, 32)
    dim3 gwt(DD / 32, DD / 32);
    dim3 bwt(32, 8);
    int splitBlocks = ELEMS / 4 / 256;

    // ---- fork: three independent front chains --------------------------
    cudaEventRecord(ev0, 0);
    cudaStreamWaitEvent(s1, ev0, 0);
    cudaStreamWaitEvent(s2, ev0, 0);

    // stream 0: q chain
    split_kernel<<<splitBlocks, 256, 0, 0>>>(q, qh, ql);
    split_wt_kernel<<<gwt, bwt, 0, 0>>>(Wq, bh_q, bl_q);
    hgemm_proj<<<gmm, 256, 2 * STG, 0>>>(qh, ql, bh_q, bl_q, bq, nullptr, qph, qpl);

    // stream s1: k chain
    ln_bf16_kernel<<<ROWS, 256, 0, s1>>>(k, ln_k_g, ln_k_b, knh, knl);
    split_wt_kernel<<<gwt, bwt, 0, s1>>>(Wk, bh_k, bl_k);
    hgemm_proj<<<gmm, 256, 2 * STG, s1>>>(knh, knl, bh_k, bl_k, bk, nullptr, kph, kpl);
    cudaEventRecord(evK, s1);

    // stream s2: v chain + Wo split
    ln_bf16_kernel<<<ROWS, 256, 0, s2>>>(v, ln_v_g, ln_v_b, vnh, vnl);
    split_wt_kernel<<<gwt, bwt, 0, s2>>>(Wv, bh_v, bl_v);
    hgemm_proj<<<gmm, 256, 2 * STG, s2>>>(vnh, vnl, bh_v, bl_v, bv, vp, nullptr, nullptr);
    split_wt_kernel<<<gwt, bwt, 0, s2>>>(Wo, bh_o, bl_o);
    transpose_split_kernel<<<dim3(32, 32, BB), bwt, 0, s2>>>(vp, vth, vtl);
    cudaEventRecord(evV, s2);

    // ---- join on stream 0 as dependencies require ----------------------
    cudaStreamWaitEvent(0, evK, 0);   // scores needs qp (s0) + kp (s1)

    if (attn_in_out) {
        float* attn = out + (size_t)ELEMS;
        hgemm_scores<<<dim3(8, 8, BB * HH), 256, 2 * STG, 0>>>(
            qph, qpl, kph, kpl, attn);
        softmax_kernel<<<BB * HH * CC, 256, 0, 0>>>(attn, attn);
        cudaStreamWaitEvent(0, evV, 0);   // ctx needs vt (s2)
        hgemm_ctx_f32p<<<dim3(1, 8, BB * HH), 256, 2 * XSTG, 0>>>(
            attn, vth, vtl, cxh, cxl);
    } else {
        cudaStreamWaitEvent(0, evV, 0);
        flash_attn_kernel<<<dim3(1, 8, BB * HH), 256, FSMEM, 0>>>(
            qph, qpl, kph, kpl, vth, vtl, cxh, cxl);
    }

    hgemm_proj<<<gmm, 256, 2 * STG, 0>>>(cxh, cxl, bh_o, bl_o, bo, proj,
                                         nullptr, nullptr);
    l2norm_kernel<<<ROWS, 256, 0, 0>>>(proj, out);
}

// round 17
// speedup vs baseline: 1.3859x; 1.3859x over previous
#include <cuda_runtime.h>
#include <cuda_bf16.h>
#include <math.h>
#include <stdint.h>

#define BB 4
#define CC 1024
#define DD 1024
#define HH 16
#define DHH 64
#define ROWS (BB*CC)              // 4096
#define ELEMS (BB*CC*DD)          // 4194304
#define ATTN_ELEMS (BB*HH*CC*CC)  // 67108864

typedef __nv_bfloat16 bf;

// ---------------- scratch (__device__ globals; no allocation allowed) -------
__device__ float g_vp[ELEMS];
__device__ float g_proj[ELEMS];
__device__ float g_attn_scratch[ATTN_ELEMS];   // only if attn not in d_out
__device__ bf g_qh[ELEMS],  g_ql[ELEMS];
__device__ bf g_knh[ELEMS], g_knl[ELEMS];
__device__ bf g_vnh[ELEMS], g_vnl[ELEMS];
__device__ bf g_qph[ELEMS], g_qpl[ELEMS];
__device__ bf g_kph[ELEMS], g_kpl[ELEMS];
__device__ bf g_vth[ELEMS], g_vtl[ELEMS];
__device__ bf g_cxh[ELEMS], g_cxl[ELEMS];
__device__ bf g_bhi[4*DD*DD], g_blo[4*DD*DD];  // per-weight split buffers

// ---------------- PTX helpers ----------------------------------------------
__device__ __forceinline__ uint32_t smem_u32(const void* p) {
    uint32_t a;
    asm("{ .reg .u64 t; cvta.to.shared.u64 t, %1; cvt.u32.u64 %0, t; }"
        : "=r"(a) : "l"(p));
    return a;
}
__device__ __forceinline__ void ldmatrix_x4(uint32_t& r0, uint32_t& r1,
                                            uint32_t& r2, uint32_t& r3,
                                            uint32_t addr) {
    asm volatile("ldmatrix.sync.aligned.m8n8.x4.shared.b16 {%0,%1,%2,%3}, [%4];"
        : "=r"(r0), "=r"(r1), "=r"(r2), "=r"(r3) : "r"(addr));
}
__device__ __forceinline__ void mma_bf16(float* d, const uint32_t* a,
                                         uint32_t b0, uint32_t b1) {
    asm volatile(
        "mma.sync.aligned.m16n8k16.row.col.f32.bf16.bf16.f32 "
        "{%0,%1,%2,%3}, {%4,%5,%6,%7}, {%8,%9}, {%0,%1,%2,%3};"
        : "+f"(d[0]), "+f"(d[1]), "+f"(d[2]), "+f"(d[3])
        : "r"(a[0]), "r"(a[1]), "r"(a[2]), "r"(a[3]), "r"(b0), "r"(b1));
}
#define CP16(dst, src) \
    asm volatile("cp.async.cg.shared.global [%0], [%1], 16;" \
        :: "r"((uint32_t)(dst)), "l"(src))
#define CP_COMMIT() asm volatile("cp.async.commit_group;" ::: "memory")
#define CP_WAIT0()  asm volatile("cp.async.wait_group 0;" ::: "memory")
#define CP_WAIT1()  asm volatile("cp.async.wait_group 1;" ::: "memory")

__device__ __forceinline__ uint32_t pack_bf2(float x, float y) {
    union { __nv_bfloat162 b2; uint32_t u; } u;
    u.b2 = __halves2bfloat162(__float2bfloat16(x), __float2bfloat16(y));
    return u.u;
}

// ---------------------------------------------------------------------------
// Generic 128x128 HMMA core: C = A[M,K] @ B^T + bias
// ---------------------------------------------------------------------------
#define GP 40
#define STG 40960
#define AHOF 0
#define ALOF 10240
#define BHOF 20480
#define BLOF 30720

__device__ __forceinline__ void hgemm128_core(
    uint32_t sb,
    const bf* __restrict__ Ahi, const bf* __restrict__ Alo, int lda,
    const bf* __restrict__ Bhi, const bf* __restrict__ Blo, int ldb,
    const float* __restrict__ bias,
    float* __restrict__ Cf, int ldcf,
    bf* __restrict__ Chi, bf* __restrict__ Clo, int ldch,
    int Ktot, int m0, int n0)
{
    int tid = threadIdx.x, wid = tid >> 5, lane = tid & 31;
    int wm = (wid >> 2) * 64, wn = (wid & 3) * 32;
    float acc[4][4][4];
    #pragma unroll
    for (int i = 0; i < 4; i++)
        #pragma unroll
        for (int j = 0; j < 4; j++)
            #pragma unroll
            for (int q = 0; q < 4; q++) acc[i][j][q] = 0.f;

    int a_row = lane & 15, a_k8 = lane >> 4;
    int b_n = (lane >> 4) * 8 + (lane & 7), b_k8 = (lane >> 3) & 1;
    int r0 = tid >> 2, c0 = tid & 3;

    auto do_load = [&](int kt, int s) {
        uint32_t base = sb + s * STG;
        #pragma unroll
        for (int i = 0; i < 2; i++) {
            int row = r0 + i * 64;
            uint32_t so = (uint32_t)(row * GP + c0 * 8) * 2;
            size_t ga = (size_t)(m0 + row) * lda + kt * 32 + c0 * 8;
            size_t gb = (size_t)(n0 + row) * ldb + kt * 32 + c0 * 8;
            CP16(base + AHOF + so, Ahi + ga);
            CP16(base + ALOF + so, Alo + ga);
            CP16(base + BHOF + so, Bhi + gb);
            CP16(base + BLOF + so, Blo + gb);
        }
    };
    auto do_compute = [&](int s) {
        uint32_t base = sb + s * STG;
        #pragma unroll
        for (int kk = 0; kk < 32; kk += 16) {
            uint32_t bh[2][4], bl[2][4];
            #pragma unroll
            for (int bt = 0; bt < 2; bt++) {
                uint32_t off = (uint32_t)((wn + bt * 16 + b_n) * GP
                                          + kk + b_k8 * 8) * 2;
                ldmatrix_x4(bh[bt][0], bh[bt][1], bh[bt][2], bh[bt][3],
                            base + BHOF + off);
                ldmatrix_x4(bl[bt][0], bl[bt][1], bl[bt][2], bl[bt][3],
                            base + BLOF + off);
            }
            #pragma unroll
            for (int mh = 0; mh < 2; mh++) {
                uint32_t ah[2][4], al[2][4];
                #pragma unroll
                for (int m2 = 0; m2 < 2; m2++) {
                    int mt = mh * 2 + m2;
                    uint32_t off = (uint32_t)((wm + mt * 16 + a_row) * GP
                                              + kk + a_k8 * 8) * 2;
                    ldmatrix_x4(ah[m2][0], ah[m2][1], ah[m2][2], ah[m2][3],
                                base + AHOF + off);
                    ldmatrix_x4(al[m2][0], al[m2][1], al[m2][2], al[m2][3],
                                base + ALOF + off);
                }
                #pragma unroll
                for (int m2 = 0; m2 < 2; m2++) {
                    int mt = mh * 2 + m2;
                    #pragma unroll
                    for (int nt = 0; nt < 4; nt++) {
                        int bt = nt >> 1, hf = (nt & 1) * 2;
                        mma_bf16(acc[mt][nt], ah[m2], bh[bt][hf], bh[bt][hf + 1]);
                        mma_bf16(acc[mt][nt], ah[m2], bl[bt][hf], bl[bt][hf + 1]);
                        mma_bf16(acc[mt][nt], al[m2], bh[bt][hf], bh[bt][hf + 1]);
                    }
                }
            }
        }
    };

    int nch = Ktot / 32;
    do_load(0, 0); CP_COMMIT();
    for (int kt = 0; kt < nch; kt++) {
        int cur = kt & 1;
        if (kt + 1 < nch) { do_load(kt + 1, cur ^ 1); CP_COMMIT(); CP_WAIT1(); }
        else              { CP_WAIT0(); }
        __syncthreads();
        do_compute(cur);
        __syncthreads();
    }

    int gr = lane >> 2, gc2 = (lane & 3) * 2;
    #pragma unroll
    for (int mt = 0; mt < 4; mt++) {
        int r = m0 + wm + mt * 16 + gr;
        #pragma unroll
        for (int nt = 0; nt < 4; nt++) {
            int c = n0 + wn + nt * 8 + gc2;
            float bx = 0.f, by = 0.f;
            if (bias) { float2 b2 = *(const float2*)(bias + c); bx = b2.x; by = b2.y; }
            float v00 = acc[mt][nt][0] + bx, v01 = acc[mt][nt][1] + by;
            float v10 = acc[mt][nt][2] + bx, v11 = acc[mt][nt][3] + by;
            if (Cf) {
                *(float2*)(Cf + (size_t)r * ldcf + c)       = make_float2(v00, v01);
                *(float2*)(Cf + (size_t)(r + 8) * ldcf + c) = make_float2(v10, v11);
            }
            if (Chi) {
                bf h00 = __float2bfloat16(v00), h01 = __float2bfloat16(v01);
                bf h10 = __float2bfloat16(v10), h11 = __float2bfloat16(v11);
                *(__nv_bfloat162*)(Chi + (size_t)r * ldch + c) =
                    __halves2bfloat162(h00, h01);
                *(__nv_bfloat162*)(Chi + (size_t)(r + 8) * ldch + c) =
                    __halves2bfloat162(h10, h11);
                *(__nv_bfloat162*)(Clo + (size_t)r * ldch + c) = __halves2bfloat162(
                    __float2bfloat16(v00 - __bfloat162float(h00)),
                    __float2bfloat16(v01 - __bfloat162float(h01)));
                *(__nv_bfloat162*)(Clo + (size_t)(r + 8) * ldch + c) = __halves2bfloat162(
                    __float2bfloat16(v10 - __bfloat162float(h10)),
                    __float2bfloat16(v11 - __bfloat162float(h11)));
            }
        }
    }
}

__global__ __launch_bounds__(256, 2) void hgemm_proj(
    const bf* __restrict__ Ahi, const bf* __restrict__ Alo,
    const bf* __restrict__ Bhi, const bf* __restrict__ Blo,
    const float* __restrict__ bias,
    float* __restrict__ Cf, bf* __restrict__ Chi, bf* __restrict__ Clo)
{
    extern __shared__ char smem[];
    hgemm128_core(smem_u32(smem), Ahi, Alo, DD, Bhi, Blo, DD, bias,
                  Cf, DD, Chi, Clo, DD, DD,
                  blockIdx.y * 128, blockIdx.x * 128);
}

// scores: per (b,h): raw = qh @ kh^T (fp32 out, no activation)
__global__ __launch_bounds__(256, 2) void hgemm_scores(
    const bf* __restrict__ qph, const bf* __restrict__ qpl,
    const bf* __restrict__ kph, const bf* __restrict__ kpl,
    float* __restrict__ attn)
{
    extern __shared__ char smem[];
    int bh = blockIdx.z, b = bh >> 4, h = bh & 15;
    size_t off = (size_t)b * CC * DD + h * DHH;
    hgemm128_core(smem_u32(smem), qph + off, qpl + off, DD,
                  kph + off, kpl + off, DD, nullptr,
                  attn + (size_t)bh * CC * CC, CC,
                  nullptr, nullptr, 0, DHH,
                  blockIdx.y * 128, blockIdx.x * 128);
}

// ---------------------------------------------------------------------------
// ctx from fp32 P: ctx = P @ vt^T; hi/lo bf16 A-fragments built in registers.
// ---------------------------------------------------------------------------
#define XPA 0
#define XBH 18432
#define XBL 23552
#define XSTG 28672

__global__ __launch_bounds__(256, 2) void hgemm_ctx_f32p(
    const float* __restrict__ P,
    const bf* __restrict__ Bh, const bf* __restrict__ Bl,
    bf* __restrict__ Chi, bf* __restrict__ Clo)
{
    extern __shared__ char smem[];
    uint32_t sb = smem_u32(smem);
    int bh = blockIdx.z, b = bh >> 4, h = bh & 15;
    const float* A  = P  + (size_t)bh * CC * CC;
    const bf* Bhi = Bh + (size_t)(b * CC + h * DHH) * CC;
    const bf* Blo = Bl + (size_t)(b * CC + h * DHH) * CC;
    int m0 = blockIdx.y * 128;

    int tid = threadIdx.x, wid = tid >> 5, lane = tid & 31;
    int wm = (wid >> 1) * 32, wn = (wid & 1) * 32;
    float acc[2][4][4];
    #pragma unroll
    for (int i = 0; i < 2; i++)
        #pragma unroll
        for (int j = 0; j < 4; j++)
            #pragma unroll
            for (int q = 0; q < 4; q++) acc[i][j][q] = 0.f;

    int b_n = (lane >> 4) * 8 + (lane & 7), b_k8 = (lane >> 3) & 1;

    auto do_load = [&](int kt, int s) {
        uint32_t base = sb + s * XSTG;
        #pragma unroll
        for (int i = 0; i < 4; i++) {
            int idx = tid + i * 256;
            int row = idx >> 3, u = idx & 7;
            CP16(base + XPA + row * 144 + u * 16,
                 A + (size_t)(m0 + row) * CC + kt * 32 + u * 4);
        }
        {
            int row = tid >> 2, c = tid & 3;
            uint32_t so = (uint32_t)(row * GP + c * 8) * 2;
            size_t gb = (size_t)row * CC + kt * 32 + c * 8;
            CP16(base + XBH + so, Bhi + gb);
            CP16(base + XBL + so, Blo + gb);
        }
    };
    auto do_compute = [&](int s) {
        uint32_t base = sb + s * XSTG;
        const float* As = (const float*)(smem + s * XSTG + XPA);
        #pragma unroll
        for (int kk = 0; kk < 32; kk += 16) {
            uint32_t bh2[2][4], bl2[2][4];
            #pragma unroll
            for (int bt = 0; bt < 2; bt++) {
                uint32_t off = (uint32_t)((wn + bt * 16 + b_n) * GP
                                          + kk + b_k8 * 8) * 2;
                ldmatrix_x4(bh2[bt][0], bh2[bt][1], bh2[bt][2], bh2[bt][3],
                            base + XBH + off);
                ldmatrix_x4(bl2[bt][0], bl2[bt][1], bl2[bt][2], bl2[bt][3],
                            base + XBL + off);
            }
            #pragma unroll
            for (int mt = 0; mt < 2; mt++) {
                int r = wm + mt * 16 + (lane >> 2);
                int c0 = kk + (lane & 3) * 2;
                float2 p0 = *(const float2*)(As + r * 36 + c0);
                float2 p1 = *(const float2*)(As + (r + 8) * 36 + c0);
                float2 p2 = *(const float2*)(As + r * 36 + c0 + 8);
                float2 p3 = *(const float2*)(As + (r + 8) * 36 + c0 + 8);
                uint32_t a_hi[4], a_lo[4];
                a_hi[0] = pack_bf2(p0.x, p0.y);
                a_hi[1] = pack_bf2(p1.x, p1.y);
                a_hi[2] = pack_bf2(p2.x, p2.y);
                a_hi[3] = pack_bf2(p3.x, p3.y);
                bf h0x = __float2bfloat16(p0.x), h0y = __float2bfloat16(p0.y);
                bf h1x = __float2bfloat16(p1.x), h1y = __float2bfloat16(p1.y);
                bf h2x = __float2bfloat16(p2.x), h2y = __float2bfloat16(p2.y);
                bf h3x = __float2bfloat16(p3.x), h3y = __float2bfloat16(p3.y);
                a_lo[0] = pack_bf2(p0.x - __bfloat162float(h0x),
                                   p0.y - __bfloat162float(h0y));
                a_lo[1] = pack_bf2(p1.x - __bfloat162float(h1x),
                                   p1.y - __bfloat162float(h1y));
                a_lo[2] = pack_bf2(p2.x - __bfloat162float(h2x),
                                   p2.y - __bfloat162float(h2y));
                a_lo[3] = pack_bf2(p3.x - __bfloat162float(h3x),
                                   p3.y - __bfloat162float(h3y));
                #pragma unroll
                for (int nt = 0; nt < 4; nt++) {
                    int bt = nt >> 1, hf = (nt & 1) * 2;
                    mma_bf16(acc[mt][nt], a_hi, bh2[bt][hf], bh2[bt][hf + 1]);
                    mma_bf16(acc[mt][nt], a_lo, bh2[bt][hf], bh2[bt][hf + 1]);
                    mma_bf16(acc[mt][nt], a_hi, bl2[bt][hf], bl2[bt][hf + 1]);
                }
            }
        }
    };

    int nch = CC / 32;
    do_load(0, 0); CP_COMMIT();
    for (int kt = 0; kt < nch; kt++) {
        int cur = kt & 1;
        if (kt + 1 < nch) { do_load(kt + 1, cur ^ 1); CP_COMMIT(); CP_WAIT1(); }
        else              { CP_WAIT0(); }
        __syncthreads();
        do_compute(cur);
        __syncthreads();
    }

    int gr = lane >> 2, gc2 = (lane & 3) * 2;
    #pragma unroll
    for (int mt = 0; mt < 2; mt++) {
        int r = m0 + wm + mt * 16 + gr;
        size_t grow0 = (size_t)(b * CC + r) * DD;
        size_t grow1 = (size_t)(b * CC + r + 8) * DD;
        #pragma unroll
        for (int nt = 0; nt < 4; nt++) {
            int c = h * DHH + wn + nt * 8 + gc2;
            float v00 = acc[mt][nt][0], v01 = acc[mt][nt][1];
            float v10 = acc[mt][nt][2], v11 = acc[mt][nt][3];
            bf h00 = __float2bfloat16(v00), h01 = __float2bfloat16(v01);
            bf h10 = __float2bfloat16(v10), h11 = __float2bfloat16(v11);
            *(__nv_bfloat162*)(Chi + grow0 + c) = __halves2bfloat162(h00, h01);
            *(__nv_bfloat162*)(Chi + grow1 + c) = __halves2bfloat162(h10, h11);
            *(__nv_bfloat162*)(Clo + grow0 + c) = __halves2bfloat162(
                __float2bfloat16(v00 - __bfloat162float(h00)),
                __float2bfloat16(v01 - __bfloat162float(h01)));
            *(__nv_bfloat162*)(Clo + grow1 + c) = __halves2bfloat162(
                __float2bfloat16(v10 - __bfloat162float(h10)),
                __float2bfloat16(v11 - __bfloat162float(h11)));
        }
    }
}

// ---------------------------------------------------------------------------
// FLASH-FUSED attention (only used when attn is NOT part of d_out)
// ---------------------------------------------------------------------------
#define QSTR 72
#define VSTR 72
#define FQH 0
#define FQL 18432
#define FKH(s) (36864 + (s) * 18432)
#define FKL(s) (FKH(s) + 9216)
#define FVH(s) (73728 + (s) * 18432)
#define FVL(s) (FVH(s) + 9216)
#define FSMEM 110592

__global__ __launch_bounds__(256, 2) void flash_attn_kernel(
    const bf* __restrict__ qph, const bf* __restrict__ qpl,
    const bf* __restrict__ kph, const bf* __restrict__ kpl,
    const bf* __restrict__ vth, const bf* __restrict__ vtl,
    bf* __restrict__ cxh, bf* __restrict__ cxl)
{
    extern __shared__ char smem[];
    uint32_t sb = smem_u32(smem);
    int bh = blockIdx.z, b = bh >> 4, h = bh & 15;
    int m0 = blockIdx.y * 128;
    int tid = threadIdx.x, wid = tid >> 5, lane = tid & 31;
    int wm = wid * 16;

    const bf* Qh = qph + (size_t)b * CC * DD + h * DHH;
    const bf* Ql = qpl + (size_t)b * CC * DD + h * DHH;
    const bf* Kh = kph + (size_t)b * CC * DD + h * DHH;
    const bf* Kl = kpl + (size_t)b * CC * DD + h * DHH;
    const bf* Vh = vth + (size_t)(b * CC + h * DHH) * CC;
    const bf* Vl = vtl + (size_t)(b * CC + h * DHH) * CC;

    auto loadQ = [&]() {
        #pragma unroll
        for (int i = 0; i < 4; i++) {
            int idx = tid + i * 256;
            int row = idx >> 3, c8 = idx & 7;
            uint32_t so = (uint32_t)(row * QSTR + c8 * 8) * 2;
            size_t g = (size_t)(m0 + row) * DD + c8 * 8;
            CP16(sb + FQH + so, Qh + g);
            CP16(sb + FQL + so, Ql + g);
        }
    };
    auto loadK = [&](int kb, int s) {
        #pragma unroll
        for (int i = 0; i < 2; i++) {
            int idx = tid + i * 256;
            int row = idx >> 3, c8 = idx & 7;
            uint32_t so = (uint32_t)(row * QSTR + c8 * 8) * 2;
            size_t g = (size_t)(kb * 64 + row) * DD + c8 * 8;
            CP16(sb + FKH(s) + so, Kh + g);
            CP16(sb + FKL(s) + so, Kl + g);
        }
    };
    auto loadV = [&](int kb, int s) {
        #pragma unroll
        for (int i = 0; i < 2; i++) {
            int idx = tid + i * 256;
            int row = idx >> 3, c8 = idx & 7;
            uint32_t so = (uint32_t)(row * VSTR + c8 * 8) * 2;
            size_t g = (size_t)row * CC + kb * 64 + c8 * 8;
            CP16(sb + FVH(s) + so, Vh + g);
            CP16(sb + FVL(s) + so, Vl + g);
        }
    };

    float O[8][4];
    #pragma unroll
    for (int g = 0; g < 8; g++)
        #pragma unroll
        for (int q = 0; q < 4; q++) O[g][q] = 0.f;
    float s_run0 = 0.f, s_run1 = 0.f;

    int a_row = lane & 15, a_k8 = lane >> 4;
    int b_n = (lane >> 4) * 8 + (lane & 7), b_k8 = (lane >> 3) & 1;

    loadQ(); loadK(0, 0); loadV(0, 0); CP_COMMIT();

    for (int kb = 0; kb < 16; kb++) {
        int s = kb & 1;
        if (kb < 15) { loadK(kb + 1, s ^ 1); loadV(kb + 1, s ^ 1); CP_COMMIT(); CP_WAIT1(); }
        else         { CP_WAIT0(); }
        __syncthreads();

        #pragma unroll
        for (int sub = 0; sub < 2; sub++) {
            float acc[4][4];
            #pragma unroll
            for (int nt = 0; nt < 4; nt++)
                #pragma unroll
                for (int q = 0; q < 4; q++) acc[nt][q] = 0.f;

            #pragma unroll
            for (int ks = 0; ks < 4; ks++) {
                uint32_t qh4[4], ql4[4];
                uint32_t offA = (uint32_t)((wm + a_row) * QSTR + ks * 16 + a_k8 * 8) * 2;
                ldmatrix_x4(qh4[0], qh4[1], qh4[2], qh4[3], sb + FQH + offA);
                ldmatrix_x4(ql4[0], ql4[1], ql4[2], ql4[3], sb + FQL + offA);
                #pragma unroll
                for (int g2 = 0; g2 < 2; g2++) {
                    int g = sub * 2 + g2;
                    uint32_t bh4[4], bl4[4];
                    uint32_t offB = (uint32_t)((g * 16 + b_n) * QSTR + ks * 16 + b_k8 * 8) * 2;
                    ldmatrix_x4(bh4[0], bh4[1], bh4[2], bh4[3], sb + FKH(s) + offB);
                    ldmatrix_x4(bl4[0], bl4[1], bl4[2], bl4[3], sb + FKL(s) + offB);
                    mma_bf16(acc[g2 * 2],     qh4, bh4[0], bh4[1]);
                    mma_bf16(acc[g2 * 2 + 1], qh4, bh4[2], bh4[3]);
                    mma_bf16(acc[g2 * 2],     qh4, bl4[0], bl4[1]);
                    mma_bf16(acc[g2 * 2 + 1], qh4, bl4[2], bl4[3]);
                    mma_bf16(acc[g2 * 2],     ql4, bh4[0], bh4[1]);
                    mma_bf16(acc[g2 * 2 + 1], ql4, bh4[2], bh4[3]);
                }
            }

            #pragma unroll
            for (int nt = 0; nt < 4; nt++)
                #pragma unroll
                for (int q = 0; q < 4; q++) {
                    float x = acc[nt][q];
                    float x2 = x * x;
                    float u = __fmaf_rn(0.044715f, x2, 1.0f);
                    float e = __expf(-1.5957691216f * x * u);
                    float sig = __frcp_rn(1.0f + e);
                    acc[nt][q] = __expf(0.125f * x * sig);
                }
            #pragma unroll
            for (int nt = 0; nt < 4; nt++) {
                s_run0 += acc[nt][0] + acc[nt][1];
                s_run1 += acc[nt][2] + acc[nt][3];
            }

            #pragma unroll
            for (int ks2 = 0; ks2 < 2; ks2++) {
                int t0 = ks2 * 2, t1 = t0 + 1;
                uint32_t a_hi[4], a_lo[4];
                {
                    float x0 = acc[t0][0], x1 = acc[t0][1];
                    float x2 = acc[t0][2], x3 = acc[t0][3];
                    float y0 = acc[t1][0], y1 = acc[t1][1];
                    float y2 = acc[t1][2], y3 = acc[t1][3];
                    a_hi[0] = pack_bf2(x0, x1);
                    a_hi[1] = pack_bf2(x2, x3);
                    a_hi[2] = pack_bf2(y0, y1);
                    a_hi[3] = pack_bf2(y2, y3);
                    bf hx0 = __float2bfloat16(x0), hx1 = __float2bfloat16(x1);
                    bf hx2 = __float2bfloat16(x2), hx3 = __float2bfloat16(x3);
                    bf hy0 = __float2bfloat16(y0), hy1 = __float2bfloat16(y1);
                    bf hy2 = __float2bfloat16(y2), hy3 = __float2bfloat16(y3);
                    a_lo[0] = pack_bf2(x0 - __bfloat162float(hx0),
                                       x1 - __bfloat162float(hx1));
                    a_lo[1] = pack_bf2(x2 - __bfloat162float(hx2),
                                       x3 - __bfloat162float(hx3));
                    a_lo[2] = pack_bf2(y0 - __bfloat162float(hy0),
                                       y1 - __bfloat162float(hy1));
                    a_lo[3] = pack_bf2(y2 - __bfloat162float(hy2),
                                       y3 - __bfloat162float(hy3));
                }
                int kstep = sub * 2 + ks2;
                #pragma unroll
                for (int g = 0; g < 4; g++) {
                    uint32_t vh4[4], vl4[4];
                    uint32_t offV = (uint32_t)((g * 16 + b_n) * VSTR
                                               + kstep * 16 + b_k8 * 8) * 2;
                    ldmatrix_x4(vh4[0], vh4[1], vh4[2], vh4[3], sb + FVH(s) + offV);
                    ldmatrix_x4(vl4[0], vl4[1], vl4[2], vl4[3], sb + FVL(s) + offV);
                    mma_bf16(O[g * 2],     a_hi, vh4[0], vh4[1]);
                    mma_bf16(O[g * 2 + 1], a_hi, vh4[2], vh4[3]);
                    mma_bf16(O[g * 2],     a_lo, vh4[0], vh4[1]);
                    mma_bf16(O[g * 2 + 1], a_lo, vh4[2], vh4[3]);
                    mma_bf16(O[g * 2],     a_hi, vl4[0], vl4[1]);
                    mma_bf16(O[g * 2 + 1], a_hi, vl4[2], vl4[3]);
                }
            }
        }
        __syncthreads();
    }

    #pragma unroll
    for (int o = 1; o <= 2; o <<= 1) {
        s_run0 += __shfl_xor_sync(0xFFFFFFFFu, s_run0, o);
        s_run1 += __shfl_xor_sync(0xFFFFFFFFu, s_run1, o);
    }
    float i0 = 1.f / s_run0, i1 = 1.f / s_run1;
    int r = m0 + wm + (lane >> 2);
    size_t row0 = (size_t)(b * CC + r) * DD;
    size_t row1 = (size_t)(b * CC + r + 8) * DD;
    #pragma unroll
    for (int g = 0; g < 8; g++) {
        int c = h * DHH + g * 8 + (lane & 3) * 2;
        float v00 = O[g][0] * i0, v01 = O[g][1] * i0;
        float v10 = O[g][2] * i1, v11 = O[g][3] * i1;
        bf h00 = __float2bfloat16(v00), h01 = __float2bfloat16(v01);
        bf h10 = __float2bfloat16(v10), h11 = __float2bfloat16(v11);
        *(__nv_bfloat162*)(cxh + row0 + c) = __halves2bfloat162(h00, h01);
        *(__nv_bfloat162*)(cxh + row1 + c) = __halves2bfloat162(h10, h11);
        *(__nv_bfloat162*)(cxl + row0 + c) = __halves2bfloat162(
            __float2bfloat16(v00 - __bfloat162float(h00)),
            __float2bfloat16(v01 - __bfloat162float(h01)));
        *(__nv_bfloat162*)(cxl + row1 + c) = __halves2bfloat162(
            __float2bfloat16(v10 - __bfloat162float(h10)),
            __float2bfloat16(v11 - __bfloat162float(h11)));
    }
}

// ---------------------------------------------------------------------------
// elementwise / reduction kernels
// ---------------------------------------------------------------------------
__global__ __launch_bounds__(256) void split_kernel(
    const float* __restrict__ x, bf* __restrict__ hi, bf* __restrict__ lo)
{
    int i = blockIdx.x * 256 + threadIdx.x;
    float4 v = ((const float4*)x)[i];
    bf h0 = __float2bfloat16(v.x), h1 = __float2bfloat16(v.y);
    bf h2 = __float2bfloat16(v.z), h3 = __float2bfloat16(v.w);
    union { __nv_bfloat162 b2[2]; uint2 u; } ph, pl;
    ph.b2[0] = __halves2bfloat162(h0, h1); ph.b2[1] = __halves2bfloat162(h2, h3);
    pl.b2[0] = __halves2bfloat162(__float2bfloat16(v.x - __bfloat162float(h0)),
                                  __float2bfloat16(v.y - __bfloat162float(h1)));
    pl.b2[1] = __halves2bfloat162(__float2bfloat16(v.z - __bfloat162float(h2)),
                                  __float2bfloat16(v.w - __bfloat162float(h3)));
    ((uint2*)hi)[i] = ph.u;
    ((uint2*)lo)[i] = pl.u;
}

// batched weight split: z selects weight; all four W -> hiT/loT slabs
__global__ void split_wt4_kernel(const float* __restrict__ W0,
                                 const float* __restrict__ W1,
                                 const float* __restrict__ W2,
                                 const float* __restrict__ W3,
                                 bf* __restrict__ hiT, bf* __restrict__ loT)
{
    __shared__ float t[32][33];
    int wsel = blockIdx.z;
    const float* W = (wsel == 0) ? W0 : (wsel == 1) ? W1 : (wsel == 2) ? W2 : W3;
    bf* hi = hiT + (size_t)wsel * DD * DD;
    bf* lo = loT + (size_t)wsel * DD * DD;
    int k0 = blockIdx.y * 32, n0 = blockIdx.x * 32;
    int tx = threadIdx.x, ty = threadIdx.y;
    #pragma unroll
    for (int j = 0; j < 4; j++)
        t[ty + j * 8][tx] = W[(size_t)(k0 + ty + j * 8) * DD + n0 + tx];
    __syncthreads();
    #pragma unroll
    for (int j = 0; j < 4; j++) {
        float x = t[tx][ty + j * 8];
        bf h = __float2bfloat16(x);
        size_t o = (size_t)(n0 + ty + j * 8) * DD + k0 + tx;
        hi[o] = h;
        lo[o] = __float2bfloat16(x - __bfloat162float(h));
    }
}

__global__ void transpose_split_kernel(const float* __restrict__ vp,
                                       bf* __restrict__ vth, bf* __restrict__ vtl)
{
    __shared__ float t[32][33];
    int b = blockIdx.z;
    int c0 = blockIdx.x * 32, n0 = blockIdx.y * 32;
    int tx = threadIdx.x, ty = threadIdx.y;
    #pragma unroll
    for (int j = 0; j < 4; j++)
        t[ty + j * 8][tx] = vp[(size_t)(b * CC + c0 + ty + j * 8) * DD + n0 + tx];
    __syncthreads();
    #pragma unroll
    for (int j = 0; j < 4; j++) {
        float x = t[tx][ty + j * 8];
        bf h = __float2bfloat16(x);
        size_t o = (size_t)(b * CC + n0 + ty + j * 8) * CC + c0 + tx;
        vth[o] = h;
        vtl[o] = __float2bfloat16(x - __bfloat162float(h));
    }
}

__global__ __launch_bounds__(256) void ln_bf16_kernel(
    const float* __restrict__ x, const float* __restrict__ gam,
    const float* __restrict__ bet, bf* __restrict__ oh, bf* __restrict__ ol)
{
    int row = blockIdx.x;
    int tid = threadIdx.x;
    const float4 v = ((const float4*)(x + (size_t)row * DD))[tid];
    float s  = v.x + v.y + v.z + v.w;
    float ss = v.x*v.x + v.y*v.y + v.z*v.z + v.w*v.w;
    #pragma unroll
    for (int o = 16; o > 0; o >>= 1) {
        s  += __shfl_xor_sync(0xFFFFFFFFu, s, o);
        ss += __shfl_xor_sync(0xFFFFFFFFu, ss, o);
    }
    __shared__ float sh_s[8], sh_ss[8];
    __shared__ float sh_m, sh_r;
    int w = tid >> 5, l = tid & 31;
    if (l == 0) { sh_s[w] = s; sh_ss[w] = ss; }
    __syncthreads();
    if (tid == 0) {
        float S = 0.f, SS = 0.f;
        #pragma unroll
        for (int i = 0; i < 8; i++) { S += sh_s[i]; SS += sh_ss[i]; }
        float m = S * (1.0f / DD);
        sh_m = m;
        sh_r = rsqrtf(SS * (1.0f / DD) - m * m + 1e-5f);
    }
    __syncthreads();
    float m = sh_m, r = sh_r;
    const float4 g4 = ((const float4*)gam)[tid];
    const float4 b4 = ((const float4*)bet)[tid];
    float y0 = (v.x - m) * r * g4.x + b4.x;
    float y1 = (v.y - m) * r * g4.y + b4.y;
    float y2 = (v.z - m) * r * g4.z + b4.z;
    float y3 = (v.w - m) * r * g4.w + b4.w;
    bf h0 = __float2bfloat16(y0), h1 = __float2bfloat16(y1);
    bf h2 = __float2bfloat16(y2), h3 = __float2bfloat16(y3);
    union { __nv_bfloat162 b2[2]; uint2 u; } ph, pl;
    ph.b2[0] = __halves2bfloat162(h0, h1); ph.b2[1] = __halves2bfloat162(h2, h3);
    pl.b2[0] = __halves2bfloat162(__float2bfloat16(y0 - __bfloat162float(h0)),
                                  __float2bfloat16(y1 - __bfloat162float(h1)));
    pl.b2[1] = __halves2bfloat162(__float2bfloat16(y2 - __bfloat162float(h2)),
                                  __float2bfloat16(y3 - __bfloat162float(h3)));
    ((uint2*)(oh + (size_t)row * DD))[tid] = ph.u;
    ((uint2*)(ol + (size_t)row * DD))[tid] = pl.u;
}

// GELU*scale + softmax (no max pass: logits bounded <= ~4.5, exp safe)
// two rows per block: warps 0-3 row0, warps 4-7 row1
__global__ __launch_bounds__(256) void softmax_kernel(
    const float* __restrict__ in, float* __restrict__ outf)
{
    size_t row = (size_t)blockIdx.x * 2 + (threadIdx.x >> 7);
    int tid = threadIdx.x & 127;
    const float* r = in + row * (size_t)CC;
    float4 v0 = ((const float4*)r)[tid];
    float4 v1 = ((const float4*)r)[tid + 128];
    const float scale = 0.125f;
    const float inv_sqrt2 = 0.70710678118654752f;
    float t0 = 0.5f * v0.x * (1.0f + erff(v0.x * inv_sqrt2)) * scale;
    float t1 = 0.5f * v0.y * (1.0f + erff(v0.y * inv_sqrt2)) * scale;
    float t2 = 0.5f * v0.z * (1.0f + erff(v0.z * inv_sqrt2)) * scale;
    float t3 = 0.5f * v0.w * (1.0f + erff(v0.w * inv_sqrt2)) * scale;
    float t4 = 0.5f * v1.x * (1.0f + erff(v1.x * inv_sqrt2)) * scale;
    float t5 = 0.5f * v1.y * (1.0f + erff(v1.y * inv_sqrt2)) * scale;
    float t6 = 0.5f * v1.z * (1.0f + erff(v1.z * inv_sqrt2)) * scale;
    float t7 = 0.5f * v1.w * (1.0f + erff(v1.w * inv_sqrt2)) * scale;

    float e0 = __expf(t0), e1 = __expf(t1), e2 = __expf(t2), e3 = __expf(t3);
    float e4 = __expf(t4), e5 = __expf(t5), e6 = __expf(t6), e7 = __expf(t7);
    float s = e0 + e1 + e2 + e3 + e4 + e5 + e6 + e7;
    #pragma unroll
    for (int o = 16; o > 0; o >>= 1)
        s += __shfl_xor_sync(0xFFFFFFFFu, s, o);
    __shared__ float shm[8];
    __shared__ float shv[2];
    int w = threadIdx.x >> 5, l = threadIdx.x & 31;
    int half = threadIdx.x >> 7;             // 0 or 1
    if (l == 0) shm[w] = s;
    __syncthreads();
    if ((threadIdx.x & 127) == 0) {
        int base = half * 4;
        float S = shm[base] + shm[base + 1] + shm[base + 2] + shm[base + 3];
        shv[half] = 1.0f / S;
    }
    __syncthreads();
    float inv = shv[half];
    float4 o0, o1;
    o0.x = e0 * inv; o0.y = e1 * inv; o0.z = e2 * inv; o0.w = e3 * inv;
    o1.x = e4 * inv; o1.y = e5 * inv; o1.z = e6 * inv; o1.w = e7 * inv;
    float* wr = outf + row * (size_t)CC;
    ((float4*)wr)[tid]       = o0;
    ((float4*)wr)[tid + 128] = o1;
}

__global__ __launch_bounds__(256) void l2norm_kernel(
    const float* __restrict__ x, float* __restrict__ y)
{
    int row = blockIdx.x;
    int tid = threadIdx.x;
    const float4 v = ((const float4*)(x + (size_t)row * DD))[tid];
    float ss = v.x*v.x + v.y*v.y + v.z*v.z + v.w*v.w;
    #pragma unroll
    for (int o = 16; o > 0; o >>= 1)
        ss += __shfl_xor_sync(0xFFFFFFFFu, ss, o);
    __shared__ float sh[8];
    __shared__ float shinv;
    int w = tid >> 5, l = tid & 31;
    if (l == 0) sh[w] = ss;
    __syncthreads();
    if (tid == 0) {
        float S = 0.f;
        #pragma unroll
        for (int i = 0; i < 8; i++) S += sh[i];
        shinv = 1.0f / fmaxf(sqrtf(S), 1e-12f);
    }
    __syncthreads();
    float inv = shinv;
    float4 o;
    o.x = v.x * inv; o.y = v.y * inv; o.z = v.z * inv; o.w = v.w * inv;
    ((float4*)(y + (size_t)row * DD))[tid] = o;
}

// ---------------------------------------------------------------------------
extern "C" void kernel_launch(void* const* d_in, const int* in_sizes, int n_in,
                              void* d_out, int out_size)
{
    const float* q      = (const float*)d_in[0];
    const float* k      = (const float*)d_in[1];
    const float* v      = (const float*)d_in[2];
    const float* ln_k_g = (const float*)d_in[3];
    const float* ln_k_b = (const float*)d_in[4];
    const float* ln_v_g = (const float*)d_in[5];
    const float* ln_v_b = (const float*)d_in[6];
    const float* Wq     = (const float*)d_in[7];
    const float* bq     = (const float*)d_in[8];
    const float* Wk     = (const float*)d_in[9];
    const float* bk     = (const float*)d_in[10];
    const float* Wv     = (const float*)d_in[11];
    const float* bv     = (const float*)d_in[12];
    const float* Wo     = (const float*)d_in[13];
    const float* bo     = (const float*)d_in[14];

    float* out = (float*)d_out;

    float *vp, *proj, *attn_scr;
    bf *qh, *ql, *knh, *knl, *vnh, *vnl, *qph, *qpl, *kph, *kpl;
    bf *vth, *vtl, *cxh, *cxl, *bhi, *blo;
    cudaGetSymbolAddress((void**)&vp,   g_vp);
    cudaGetSymbolAddress((void**)&proj, g_proj);
    cudaGetSymbolAddress((void**)&attn_scr, g_attn_scratch);
    cudaGetSymbolAddress((void**)&qh,  g_qh);  cudaGetSymbolAddress((void**)&ql,  g_ql);
    cudaGetSymbolAddress((void**)&knh, g_knh); cudaGetSymbolAddress((void**)&knl, g_knl);
    cudaGetSymbolAddress((void**)&vnh, g_vnh); cudaGetSymbolAddress((void**)&vnl, g_vnl);
    cudaGetSymbolAddress((void**)&qph, g_qph); cudaGetSymbolAddress((void**)&qpl, g_qpl);
    cudaGetSymbolAddress((void**)&kph, g_kph); cudaGetSymbolAddress((void**)&kpl, g_kpl);
    cudaGetSymbolAddress((void**)&vth, g_vth); cudaGetSymbolAddress((void**)&vtl, g_vtl);
    cudaGetSymbolAddress((void**)&cxh, g_cxh); cudaGetSymbolAddress((void**)&cxl, g_cxl);
    cudaGetSymbolAddress((void**)&bhi, g_bhi); cudaGetSymbolAddress((void**)&blo, g_blo);

    bf *bh_q = bhi,                   *bl_q = blo;
    bf *bh_k = bhi + (size_t)DD*DD,   *bl_k = blo + (size_t)DD*DD;
    bf *bh_v = bhi + (size_t)2*DD*DD, *bl_v = blo + (size_t)2*DD*DD;
    bf *bh_o = bhi + (size_t)3*DD*DD, *bl_o = blo + (size_t)3*DD*DD;

    int attn_in_out = (out_size >= (int)(ELEMS + ATTN_ELEMS));

    cudaFuncSetAttribute(hgemm_proj,
        cudaFuncAttributeMaxDynamicSharedMemorySize, 2 * STG);
    cudaFuncSetAttribute(hgemm_scores,
        cudaFuncAttributeMaxDynamicSharedMemorySize, 2 * STG);
    cudaFuncSetAttribute(hgemm_ctx_f32p,
        cudaFuncAttributeMaxDynamicSharedMemorySize, 2 * XSTG);
    cudaFuncSetAttribute(flash_attn_kernel,
        cudaFuncAttributeMaxDynamicSharedMemorySize, FSMEM);

    dim3 gmm(DD / 128, ROWS / 128);      // (8, 32)
    dim3 gwt4(DD / 32, DD / 32, 4);
    dim3 bwt(32, 8);
    int splitBlocks = ELEMS / 4 / 256;

    // single stream, dependency-ordered
    ln_bf16_kernel<<<ROWS, 256>>>(k, ln_k_g, ln_k_b, knh, knl);
    ln_bf16_kernel<<<ROWS, 256>>>(v, ln_v_g, ln_v_b, vnh, vnl);
    split_kernel<<<splitBlocks, 256>>>(q, qh, ql);
    split_wt4_kernel<<<gwt4, bwt>>>(Wq, Wk, Wv, Wo, bhi, blo);
    hgemm_proj<<<gmm, 256, 2 * STG>>>(qh, ql, bh_q, bl_q, bq, nullptr, qph, qpl);
    hgemm_proj<<<gmm, 256, 2 * STG>>>(knh, knl, bh_k, bl_k, bk, nullptr, kph, kpl);
    hgemm_proj<<<gmm, 256, 2 * STG>>>(vnh, vnl, bh_v, bl_v, bv, vp, nullptr, nullptr);
    transpose_split_kernel<<<dim3(32, 32, BB), bwt>>>(vp, vth, vtl);

    if (attn_in_out) {
        float* attn = out + (size_t)ELEMS;
        hgemm_scores<<<dim3(8, 8, BB * HH), 256, 2 * STG>>>(qph, qpl, kph, kpl, attn);
        softmax_kernel<<<BB * HH * CC / 2, 256>>>(attn, attn);
        hgemm_ctx_f32p<<<dim3(1, 8, BB * HH), 256, 2 * XSTG>>>(
            attn, vth, vtl, cxh, cxl);
    } else {
        flash_attn_kernel<<<dim3(1, 8, BB * HH), 256, FSMEM>>>(
            qph, qpl, kph, kpl, vth, vtl, cxh, cxl);
    }

    hgemm_proj<<<gmm, 256, 2 * STG>>>(cxh, cxl, bh_o, bl_o, bo, proj, nullptr, nullptr);
    l2norm_kernel<<<ROWS, 256>>>(proj, out);
}